// round 6
// baseline (speedup 1.0000x reference)
#include <cuda_runtime.h>

#define DIMQ 64
#define H1   128
#define H2   16
#define NC   4
#define VCH  5
#define IMGD 224
#define PP   (IMGD*IMGD)   // 50176
#define BB   32

// Per-batch softmax attention weights (B x 4)
__device__ float g_att[BB * NC];

// Dynamic smem layout (floats). W1 stored TRANSPOSED [128][68] (pad 68),
// W2 TRANSPOSED [16][132] (pad 132). All offsets multiple of 4 floats.
#define OFF_W1TQ 0
#define OFF_W1TK (OFF_W1TQ + 128*68)      // 8704
#define OFF_W2TQ (OFF_W1TK + 128*68)      // 17408
#define OFF_W2TK (OFF_W2TQ + 16*132)      // 19520
#define OFF_B1Q  (OFF_W2TK + 16*132)      // 21632
#define OFF_B1K  (OFF_B1Q + 128)
#define OFF_B2Q  (OFF_B1K + 128)
#define OFF_B2K  (OFF_B2Q + 16)
#define OFF_GQ   (OFF_B2K + 16)
#define OFF_GK   (OFF_GQ  + 16)
#define OFF_BEQ  (OFF_GK  + 16)
#define OFF_BEK  (OFF_BEQ + 16)
#define OFF_X    (OFF_BEK + 16)           // 5*64
#define OFF_H1   (OFF_X   + 320)          // 5*128
#define OFF_H2P  (OFF_H1  + 640)          // 160
#define OFF_H2   (OFF_H2P + 160)          // 80
#define OFF_EMB  (OFF_H2  + 80)           // 80
#define OFF_LOG  (OFF_EMB + 80)           // 4
#define OFF_MD   (OFF_LOG + 4)            // 4
#define SMEM_FLOATS (OFF_MD + 4)
#define SMEM_BYTES  (SMEM_FLOATS * 4)

// ---------------------------------------------------------------------------
// Kernel A (PDL primary): one block per batch, 256 threads.
// Single front-batched staging phase (weights transposed, biases, inputs, md),
// then all-LDS.128 compute. Triggers programmatic launch completion at entry
// so fuse_kernel's grid can launch and co-reside immediately.
// ---------------------------------------------------------------------------
__global__ void __launch_bounds__(256)
mlp_att_kernel(
    const float* __restrict__ q,    // (B, 64, 1)
    const float* __restrict__ k,    // (B, 64, 1, 4)
    const int*   __restrict__ md,   // (B, 4)
    const float* __restrict__ Wq1, const float* __restrict__ bq1,
    const float* __restrict__ Wq2, const float* __restrict__ bq2,
    const float* __restrict__ gq,  const float* __restrict__ betaq,
    const float* __restrict__ Wk1, const float* __restrict__ bk1,
    const float* __restrict__ Wk2, const float* __restrict__ bk2,
    const float* __restrict__ gk,  const float* __restrict__ betak)
{
    cudaTriggerProgrammaticLaunchCompletion();

    extern __shared__ float sm[];
    const int b   = blockIdx.x;
    const int tid = threadIdx.x;

    // ---- Staging phase: everything global -> smem, fully front-batched ----
    // W1 (64x128, j fast) -> W1T[j][d], rows padded to 68
    {
        const float4* s1q = reinterpret_cast<const float4*>(Wq1);
        const float4* s1k = reinterpret_cast<const float4*>(Wk1);
        #pragma unroll
        for (int i = 0; i < 8; i++) {
            int f4 = tid + i * 256;          // 0..2047
            int d  = f4 >> 5;                // 32 float4 per d-row
            int j  = (f4 & 31) * 4;
            float4 a = s1q[f4];
            float* dq = sm + OFF_W1TQ;
            dq[(j+0)*68 + d] = a.x; dq[(j+1)*68 + d] = a.y;
            dq[(j+2)*68 + d] = a.z; dq[(j+3)*68 + d] = a.w;
            float4 c = s1k[f4];
            float* dk = sm + OFF_W1TK;
            dk[(j+0)*68 + d] = c.x; dk[(j+1)*68 + d] = c.y;
            dk[(j+2)*68 + d] = c.z; dk[(j+3)*68 + d] = c.w;
        }
        // W2 (128x16, o fast) -> W2T[o][j], rows padded to 132
        const float4* s2q = reinterpret_cast<const float4*>(Wq2);
        const float4* s2k = reinterpret_cast<const float4*>(Wk2);
        #pragma unroll
        for (int i = 0; i < 2; i++) {
            int f4 = tid + i * 256;          // 0..511
            int j  = f4 >> 2;                // 4 float4 per j-row
            int o  = (f4 & 3) * 4;
            float4 a = s2q[f4];
            float* dq = sm + OFF_W2TQ;
            dq[(o+0)*132 + j] = a.x; dq[(o+1)*132 + j] = a.y;
            dq[(o+2)*132 + j] = a.z; dq[(o+3)*132 + j] = a.w;
            float4 c = s2k[f4];
            float* dk = sm + OFF_W2TK;
            dk[(o+0)*132 + j] = c.x; dk[(o+1)*132 + j] = c.y;
            dk[(o+2)*132 + j] = c.z; dk[(o+3)*132 + j] = c.w;
        }
    }
    // biases / gains / betas / md
    if (tid < 128) {
        sm[OFF_B1Q + tid] = bq1[tid];
        sm[OFF_B1K + tid] = bk1[tid];
    } else if (tid < 144) {
        int t = tid - 128;
        sm[OFF_B2Q + t] = bq2[t];  sm[OFF_B2K + t] = bk2[t];
        sm[OFF_GQ  + t] = gq[t];   sm[OFF_GK  + t] = gk[t];
        sm[OFF_BEQ + t] = betaq[t];sm[OFF_BEK + t] = betak[t];
    } else if (tid < 148) {
        int t = tid - 144;
        reinterpret_cast<int*>(sm + OFF_MD)[t] = md[b * NC + t];
    }
    // inputs: row 0 = q, rows 1..4 = k contrasts
    for (int i = tid; i < 5 * DIMQ; i += 256) {
        int row = i >> 6;
        int d   = i & 63;
        sm[OFF_X + i] = (row == 0) ? q[b * DIMQ + d]
                                   : k[(b * DIMQ + d) * NC + (row - 1)];
    }
    __syncthreads();

    // ---- Layer 1: 640 units, all LDS.128, conflict-free (stride 68) ----
    #pragma unroll
    for (int it = 0; it < 3; it++) {
        int u = tid + it * 256;
        if (u < 640) {
            int row = u >> 7;
            int j   = u & 127;
            const float* wT = sm + (row == 0 ? OFF_W1TQ : OFF_W1TK) + j * 68;
            const float* x  = sm + OFF_X + row * DIMQ;
            float acc = sm[(row == 0 ? OFF_B1Q : OFF_B1K) + j];
            #pragma unroll
            for (int d = 0; d < DIMQ; d += 4) {
                float4 w4 = *reinterpret_cast<const float4*>(wT + d);
                float4 x4 = *reinterpret_cast<const float4*>(x + d);
                acc = fmaf(x4.x, w4.x, acc);
                acc = fmaf(x4.y, w4.y, acc);
                acc = fmaf(x4.z, w4.z, acc);
                acc = fmaf(x4.w, w4.w, acc);
            }
            sm[OFF_H1 + row * H1 + j] = (acc > 0.0f) ? acc : 0.1f * acc;
        }
    }
    __syncthreads();

    // ---- Layer 2: 80 units, split-K halves, LDS.128 ----
    if (tid < 160) {
        int idx  = tid % 80;
        int half = tid / 80;
        int row  = idx >> 4;
        int o    = idx & 15;
        const float* w = sm + (row == 0 ? OFF_W2TQ : OFF_W2TK) + o * 132 + half * 64;
        const float* h = sm + OFF_H1 + row * H1 + half * 64;
        float acc = (half == 0) ? sm[(row == 0 ? OFF_B2Q : OFF_B2K) + o] : 0.0f;
        #pragma unroll
        for (int j = 0; j < 64; j += 4) {
            float4 w4 = *reinterpret_cast<const float4*>(w + j);
            float4 h4 = *reinterpret_cast<const float4*>(h + j);
            acc = fmaf(h4.x, w4.x, acc);
            acc = fmaf(h4.y, w4.y, acc);
            acc = fmaf(h4.z, w4.z, acc);
            acc = fmaf(h4.w, w4.w, acc);
        }
        sm[OFF_H2P + half * 80 + idx] = acc;
    }
    __syncthreads();

    if (tid < 80)
        sm[OFF_H2 + tid] = sm[OFF_H2P + tid] + sm[OFF_H2P + 80 + tid];
    __syncthreads();

    // ---- LayerNorm(16) per row ----
    if (tid < 80) {
        int row = tid >> 4;
        int o   = tid & 15;
        const float* G  = sm + (row == 0 ? OFF_GQ  : OFF_GK);
        const float* BE = sm + (row == 0 ? OFF_BEQ : OFF_BEK);
        const float* h2 = sm + OFF_H2 + row * H2;
        float mu = 0.0f;
        #pragma unroll
        for (int j = 0; j < H2; j++) mu += h2[j];
        mu *= (1.0f / H2);
        float var = 0.0f;
        #pragma unroll
        for (int j = 0; j < H2; j++) {
            float d = h2[j] - mu;
            var = fmaf(d, d, var);
        }
        var *= (1.0f / H2);
        sm[OFF_EMB + tid] = (h2[o] - mu) * rsqrtf(var + 1e-5f) * G[o] + BE[o];
    }
    __syncthreads();

    // ---- Logits ----
    if (tid < NC) {
        float acc = 0.0f;
        #pragma unroll
        for (int o = 0; o < H2; o++)
            acc = fmaf(sm[OFF_EMB + o], sm[OFF_EMB + (1 + tid) * H2 + o], acc);
        int m = reinterpret_cast<const int*>(sm + OFF_MD)[tid];
        sm[OFF_LOG + tid] = (acc * 0.125f - (float)m * 1.0e5f) * 0.1f;
    }
    __syncthreads();

    // ---- Softmax -> g_att ----
    if (tid == 0) {
        float l0 = sm[OFF_LOG + 0], l1 = sm[OFF_LOG + 1],
              l2 = sm[OFF_LOG + 2], l3 = sm[OFF_LOG + 3];
        float mx = fmaxf(fmaxf(l0, l1), fmaxf(l2, l3));
        float e0 = __expf(l0 - mx), e1 = __expf(l1 - mx),
              e2 = __expf(l2 - mx), e3 = __expf(l3 - mx);
        float inv = 1.0f / (e0 + e1 + e2 + e3);
        g_att[b * NC + 0] = e0 * inv;
        g_att[b * NC + 1] = e1 * inv;
        g_att[b * NC + 2] = e2 * inv;
        g_att[b * NC + 3] = e3 * inv;
    }
}

// ---------------------------------------------------------------------------
// Kernel B (PDL secondary): masked renorm + fuse. 4 px/thread, 128-bit LD/ST,
// streaming cache hints. Independent mask loads issue BEFORE the grid
// dependency sync so kernel A hides under them.
// ---------------------------------------------------------------------------
__global__ void __launch_bounds__(256)
fuse_kernel(
    const float* __restrict__ v,     // (B, VCH, P, C)
    const float* __restrict__ mask,  // (B, P, C)
    float*       __restrict__ out)   // [fused (B,VCH,P) | attention (B,C,P)]
{
    const int b  = blockIdx.y;
    const int p0 = (blockIdx.x * 256 + threadIdx.x) * 4;   // 4 consecutive pixels

    // Independent prefix: mask loads (do NOT need kernel A's output)
    const float4* mp = reinterpret_cast<const float4*>(mask + ((size_t)b * PP + p0) * NC);
    float4 m[4];
    #pragma unroll
    for (int px = 0; px < 4; px++) m[px] = __ldcs(mp + px);

    // Wait for kernel A's g_att to be visible
    cudaGridDependencySynchronize();

    const float4 att = *reinterpret_cast<const float4*>(&g_att[b * NC]);

    float w[4][4];
    #pragma unroll
    for (int px = 0; px < 4; px++) {
        float w0 = att.x * m[px].x;
        float w1 = att.y * m[px].y;
        float w2 = att.z * m[px].z;
        float w3 = att.w * m[px].w;
        float inv = 1.0f / (w0 + w1 + w2 + w3 + 1e-8f);
        w[px][0] = w0 * inv;
        w[px][1] = w1 * inv;
        w[px][2] = w2 * inv;
        w[px][3] = w3 * inv;
    }

    const size_t fbase = (size_t)b * VCH * PP;
    #pragma unroll
    for (int vc = 0; vc < VCH; vc++) {
        const float4* vp = reinterpret_cast<const float4*>(
            v + ((size_t)(b * VCH + vc) * PP + p0) * NC);
        float4 x0 = __ldcs(vp + 0);
        float4 x1 = __ldcs(vp + 1);
        float4 x2 = __ldcs(vp + 2);
        float4 x3 = __ldcs(vp + 3);
        float4 f;
        f.x = fmaf(w[0][3], x0.w, fmaf(w[0][2], x0.z, fmaf(w[0][1], x0.y, w[0][0] * x0.x)));
        f.y = fmaf(w[1][3], x1.w, fmaf(w[1][2], x1.z, fmaf(w[1][1], x1.y, w[1][0] * x1.x)));
        f.z = fmaf(w[2][3], x2.w, fmaf(w[2][2], x2.z, fmaf(w[2][1], x2.y, w[2][0] * x2.x)));
        f.w = fmaf(w[3][3], x3.w, fmaf(w[3][2], x3.z, fmaf(w[3][1], x3.y, w[3][0] * x3.x)));
        __stcs(reinterpret_cast<float4*>(out + fbase + (size_t)vc * PP + p0), f);
    }

    const size_t abase = (size_t)BB * VCH * PP + (size_t)b * NC * PP + p0;
    #pragma unroll
    for (int c = 0; c < NC; c++) {
        float4 a;
        a.x = w[0][c]; a.y = w[1][c]; a.z = w[2][c]; a.w = w[3][c];
        __stcs(reinterpret_cast<float4*>(out + abase + (size_t)c * PP), a);
    }
}

// ---------------------------------------------------------------------------
// Launch. Input order: q, k, v, mask, modality_dropout,
// Wq1, bq1, Wq2, bq2, gq, betaq, Wk1, bk1, Wk2, bk2, gk, betak
// ---------------------------------------------------------------------------
extern "C" void kernel_launch(void* const* d_in, const int* in_sizes, int n_in,
                              void* d_out, int out_size)
{
    const float* q     = (const float*)d_in[0];
    const float* k     = (const float*)d_in[1];
    const float* v     = (const float*)d_in[2];
    const float* mask  = (const float*)d_in[3];
    const int*   md    = (const int*)  d_in[4];
    const float* Wq1   = (const float*)d_in[5];
    const float* bq1   = (const float*)d_in[6];
    const float* Wq2   = (const float*)d_in[7];
    const float* bq2   = (const float*)d_in[8];
    const float* gq    = (const float*)d_in[9];
    const float* betaq = (const float*)d_in[10];
    const float* Wk1   = (const float*)d_in[11];
    const float* bk1   = (const float*)d_in[12];
    const float* Wk2   = (const float*)d_in[13];
    const float* bk2   = (const float*)d_in[14];
    const float* gk    = (const float*)d_in[15];
    const float* betak = (const float*)d_in[16];
    float* out = (float*)d_out;

    static bool attr_set = false;
    if (!attr_set) {
        cudaFuncSetAttribute(mlp_att_kernel,
                             cudaFuncAttributeMaxDynamicSharedMemorySize,
                             SMEM_BYTES);
        attr_set = true;
    }

    mlp_att_kernel<<<BB, 256, SMEM_BYTES>>>(q, k, md,
                                            Wq1, bq1, Wq2, bq2, gq, betaq,
                                            Wk1, bk1, Wk2, bk2, gk, betak);

    // fuse as PDL secondary: launches while mlp_att_kernel is still running.
    cudaLaunchConfig_t cfg = {};
    cfg.gridDim  = dim3(PP / 1024, BB);   // 49 x 32
    cfg.blockDim = dim3(256);
    cfg.dynamicSmemBytes = 0;
    cfg.stream = 0;
    cudaLaunchAttribute at[1];
    at[0].id = cudaLaunchAttributeProgrammaticStreamSerialization;
    at[0].val.programmaticStreamSerializationAllowed = 1;
    cfg.attrs = at;
    cfg.numAttrs = 1;
    cudaLaunchKernelEx(&cfg, fuse_kernel, v, mask, out);
}